// round 8
// baseline (speedup 1.0000x reference)
#include <cuda_runtime.h>
#include <cuda_fp16.h>

#define MAXN 100000
#define EMAX 6400000
#define SCAN_CHUNK 2048   // 512 threads x int4
#define MAXBLK 64

// Static scratch
__device__ float  d_x8[MAXN * 8];       // x padded to 8 (32B rows)
__device__ float  d_agg1[MAXN * 8];     // x + sum x[src]
__device__ __half d_g2[MAXN * 32];      // g = h_A @ w1b, fp16 (64B rows)
__device__ int    d_deg[MAXN + 4];      // zero at entry of every call
__device__ int    d_off[MAXN + 8];      // exclusive prefix; d_off[N] = E
__device__ int    d_rank[EMAX];         // edge's rank within its dst bucket
__device__ int    d_srcs[EMAX];         // CSR: sources grouped by dst
__device__ int    d_incl[MAXBLK];       // lookback: inclusive block prefix
__device__ int    d_flag[MAXBLK];       // lookback: ready flags
__device__ float2 d_sc[MAXN];

// kH: histogram of dst + per-edge rank; also x8 init and flag zeroing. 2 edges/thread.
__global__ void __launch_bounds__(256) kH_hist(const int* __restrict__ ei,
                                               const float* __restrict__ x,
                                               int E, int N) {
    int t = blockIdx.x * blockDim.x + threadIdx.x;
    if (t < MAXBLK) d_flag[t] = 0;
    if (t < N) {   // x8 init
        const float* xr = x + (size_t)t * 7;
        float4 lo = make_float4(__ldg(xr), __ldg(xr + 1), __ldg(xr + 2), __ldg(xr + 3));
        float4 hi = make_float4(__ldg(xr + 4), __ldg(xr + 5), __ldg(xr + 6), 0.f);
        ((float4*)(d_x8 + (size_t)t * 8))[0] = lo;
        ((float4*)(d_x8 + (size_t)t * 8))[1] = hi;
    }
    int e0 = 2 * t;
    if (e0 + 1 < E) {
        int2 d = *(const int2*)(ei + E + e0);
        int r0 = atomicAdd(&d_deg[d.x], 1);
        int r1 = atomicAdd(&d_deg[d.y], 1);
        *(int2*)(d_rank + e0) = make_int2(r0, r1);
    } else if (e0 < E) {
        int d = __ldg(ei + E + e0);
        d_rank[e0] = atomicAdd(&d_deg[d], 1);
    }
}

// kScan: single-kernel decoupled-lookback exclusive scan of d_deg -> d_off
__global__ void __launch_bounds__(512) kScan(int N, int NB) {
    __shared__ int s_w[16];
    __shared__ int s_prev;
    int tid = threadIdx.x, lane = tid & 31, wid = tid >> 5;
    int b = blockIdx.x;
    int base = b * SCAN_CHUNK + tid * 4;
    int4 v = make_int4(0, 0, 0, 0);
    if (base < N) v = *(const int4*)(d_deg + base);
    int t1 = v.x + v.y, t2 = t1 + v.z, tot = t2 + v.w;
    int scan = tot;
#pragma unroll
    for (int o = 1; o < 32; o <<= 1) {
        int nv = __shfl_up_sync(~0u, scan, o);
        if (lane >= o) scan += nv;
    }
    if (lane == 31) s_w[wid] = scan;
    __syncthreads();
    if (wid == 0 && lane < 16) {
        int w = s_w[lane];
#pragma unroll
        for (int o = 1; o < 16; o <<= 1) {
            int nv = __shfl_up_sync(0xffffu, w, o);
            if (lane >= o) w += nv;
        }
        s_w[lane] = w;
    }
    __syncthreads();
    int btot = s_w[15];
    if (tid == 0) {
        int prev = 0;
        if (b > 0) {
            while (((volatile int*)d_flag)[b - 1] == 0) {}
            __threadfence();
            prev = ((volatile int*)d_incl)[b - 1];
        }
        d_incl[b] = prev + btot;
        __threadfence();
        ((volatile int*)d_flag)[b] = 1;
        s_prev = prev;
        if (b == NB - 1) d_off[N] = prev + btot;
    }
    __syncthreads();
    int excl = scan - tot + (wid > 0 ? s_w[wid - 1] : 0) + s_prev;
    if (base < N)
        *(int4*)(d_off + base) = make_int4(excl, excl + v.x, excl + t1, excl + t2);
}

// kP: place srcs into CSR (no atomics); re-zero d_deg for the next call. 2 edges/thread.
__global__ void __launch_bounds__(256) kP_place(const int* __restrict__ ei, int E, int N) {
    int t = blockIdx.x * blockDim.x + threadIdx.x;
    if (t < N) d_deg[t] = 0;
    int e0 = 2 * t;
    if (e0 + 1 < E) {
        int2 s = *(const int2*)(ei + e0);
        int2 d = *(const int2*)(ei + E + e0);
        int2 r = *(const int2*)(d_rank + e0);
        d_srcs[__ldg(d_off + d.x) + r.x] = s.x;
        d_srcs[__ldg(d_off + d.y) + r.y] = s.y;
    } else if (e0 < E) {
        d_srcs[__ldg(d_off + __ldg(ei + E + e0)) + d_rank[e0]] = __ldg(ei + e0);
    }
}

// kE: agg1[n] = x8[n] + sum x8[src].  8 lanes/node, 4 nodes/warp.
__global__ void __launch_bounds__(256) kE_agg1(int N) {
    int tid = blockIdx.x * blockDim.x + threadIdx.x;
    int node = tid >> 3;
    int j = tid & 7;
    if (node >= N) return;
    int beg = __ldg(d_off + node), end = __ldg(d_off + node + 1);
    float acc = d_x8[(size_t)node * 8 + j];
    int i = beg;
    for (; i + 1 < end; i += 2) {
        int s0 = __ldg(d_srcs + i);
        int s1 = __ldg(d_srcs + i + 1);
        acc += __ldg(d_x8 + (size_t)s0 * 8 + j);
        acc += __ldg(d_x8 + (size_t)s1 * 8 + j);
    }
    if (i < end) acc += __ldg(d_x8 + (size_t)__ldg(d_srcs + i) * 8 + j);
    d_agg1[(size_t)node * 8 + j] = acc;
}

// k2: per node: t[7] -> relu(t@w1a+b1a) -> @w2a+b2a -> relu -> @w1b = g[32] (fp16 out)
__global__ void __launch_bounds__(128) k2_mlpA(
    const float* __restrict__ w1a, const float* __restrict__ b1a,
    const float* __restrict__ w2a, const float* __restrict__ b2a,
    const float* __restrict__ w1b, int N) {
    __shared__ float s_w1a[7 * 64];
    __shared__ float s_b1a[64];
    __shared__ float s_w2a[64 * 64];
    __shared__ float s_b2a[64];
    __shared__ float s_w1b[64 * 32];
    for (int i = threadIdx.x; i < 112; i += 128)
        ((float4*)s_w1a)[i] = __ldg((const float4*)w1a + i);
    if (threadIdx.x < 64) { s_b1a[threadIdx.x] = b1a[threadIdx.x]; s_b2a[threadIdx.x] = b2a[threadIdx.x]; }
    for (int i = threadIdx.x; i < 1024; i += 128)
        ((float4*)s_w2a)[i] = __ldg((const float4*)w2a + i);
    for (int i = threadIdx.x; i < 512; i += 128)
        ((float4*)s_w1b)[i] = __ldg((const float4*)w1b + i);
    __syncthreads();

    int n = blockIdx.x * 128 + threadIdx.x;
    if (n >= N) return;

    float tin[7];
    const float* tr = d_agg1 + (size_t)n * 8;
#pragma unroll
    for (int i = 0; i < 7; i++) tin[i] = tr[i];

    float acc[64];
#pragma unroll
    for (int j = 0; j < 64; j++) acc[j] = 0.f;
#pragma unroll 1
    for (int k = 0; k < 64; k++) {
        float h = s_b1a[k];
#pragma unroll
        for (int i = 0; i < 7; i++) h = fmaf(tin[i], s_w1a[i * 64 + k], h);
        h = fmaxf(h, 0.f);
#pragma unroll
        for (int j = 0; j < 64; j++) acc[j] = fmaf(h, s_w2a[k * 64 + j], acc[j]);
    }

    float g[32];
#pragma unroll
    for (int j = 0; j < 32; j++) g[j] = 0.f;
#pragma unroll 1
    for (int k = 0; k < 64; k++) {
        float h = fmaxf(acc[k] + s_b2a[k], 0.f);
#pragma unroll
        for (int j = 0; j < 32; j++) g[j] = fmaf(h, s_w1b[k * 32 + j], g[j]);
    }

    half2 t16[16];
#pragma unroll
    for (int i = 0; i < 16; i++) t16[i] = __floats2half2_rn(g[2 * i], g[2 * i + 1]);
    uint4* dst = (uint4*)(d_g2 + (size_t)n * 32);
#pragma unroll
    for (int q = 0; q < 4; q++) dst[q] = ((uint4*)t16)[q];
}

// kF: warp/node: agg2 = g[n] + sum g[src] (8 groups x 4 lanes x 8 halves), fused mlpB + score
__global__ void __launch_bounds__(256) kF_agg2_mlpB(
    const float* __restrict__ b1b, const float* __restrict__ w2b,
    const float* __restrict__ b2b, const float* __restrict__ ws, int N) {
    __shared__ float s_w2b[32 * 32];
    ((float4*)s_w2b)[threadIdx.x] = __ldg((const float4*)w2b + threadIdx.x);
    __syncthreads();

    int lane = threadIdx.x & 31;
    int grp = lane >> 2;          // 0..7
    int j = lane & 3;             // dims [8j, 8j+8)
    int node = blockIdx.x * 8 + (threadIdx.x >> 5);
    if (node >= N) return;

    int beg = __ldg(d_off + node), end = __ldg(d_off + node + 1);
    float acc[8];
#pragma unroll
    for (int m = 0; m < 8; m++) acc[m] = 0.f;

    if (grp == 0) {   // self term
        uint4 r = *(const uint4*)(d_g2 + (size_t)node * 32 + j * 8);
        const half2* h = (const half2*)&r;
#pragma unroll
        for (int m = 0; m < 4; m++) {
            float2 f = __half22float2(h[m]);
            acc[2 * m] += f.x; acc[2 * m + 1] += f.y;
        }
    }
    for (int i = beg + grp; i < end; i += 8) {
        int s = __ldg(d_srcs + i);
        uint4 r = __ldg((const uint4*)(d_g2 + (size_t)s * 32 + j * 8));
        const half2* h = (const half2*)&r;
#pragma unroll
        for (int m = 0; m < 4; m++) {
            float2 f = __half22float2(h[m]);
            acc[2 * m] += f.x; acc[2 * m + 1] += f.y;
        }
    }
    // reduce across 8 groups (xor lane bits 2,3,4)
#pragma unroll
    for (int o = 4; o <= 16; o <<= 1) {
#pragma unroll
        for (int m = 0; m < 8; m++) acc[m] += __shfl_xor_sync(~0u, acc[m], o);
    }
    // a = relu(acc + b1b[8j..8j+8))
    float4 bb0 = __ldg((const float4*)b1b + 2 * j);
    float4 bb1 = __ldg((const float4*)b1b + 2 * j + 1);
    float a[8];
    a[0] = fmaxf(acc[0] + bb0.x, 0.f); a[1] = fmaxf(acc[1] + bb0.y, 0.f);
    a[2] = fmaxf(acc[2] + bb0.z, 0.f); a[3] = fmaxf(acc[3] + bb0.w, 0.f);
    a[4] = fmaxf(acc[4] + bb1.x, 0.f); a[5] = fmaxf(acc[5] + bb1.y, 0.f);
    a[6] = fmaxf(acc[6] + bb1.z, 0.f); a[7] = fmaxf(acc[7] + bb1.w, 0.f);

    // h2[lane] = b2b[lane] + sum_k a[k] * w2b[k*32+lane]; a[k] in lane k>>3, reg k&7
    float h2 = __ldg(b2b + lane);
#pragma unroll
    for (int k = 0; k < 32; k++) {
        float ak = __shfl_sync(~0u, a[k & 7], k >> 3);
        h2 = fmaf(ak, s_w2b[k * 32 + lane], h2);
    }
    float s0 = h2 * __ldg(ws + lane);
    float s1 = h2 * __ldg(ws + 32 + lane);
#pragma unroll
    for (int o = 16; o > 0; o >>= 1) {
        s0 += __shfl_down_sync(~0u, s0, o);
        s1 += __shfl_down_sync(~0u, s1, o);
    }
    if (lane == 0) d_sc[node] = make_float2(s0, s1);
}

// k5: out[i] = sigmoid(s0[c0] + s1[c1] + bs).  2 candidates per thread.
__global__ void k5_score(const int* __restrict__ cand, const float* __restrict__ bs,
                         float* __restrict__ out, int C) {
    int i = blockIdx.x * blockDim.x + threadIdx.x;
    int npair = C >> 1;
    float b = __ldg(bs);
    if (i < npair) {
        int4 c = __ldg((const int4*)cand + i);
        float z0 = d_sc[c.x].x + d_sc[c.y].y + b;
        float z1 = d_sc[c.z].x + d_sc[c.w].y + b;
        ((float2*)out)[i] = make_float2(1.f / (1.f + __expf(-z0)),
                                        1.f / (1.f + __expf(-z1)));
    }
    if ((C & 1) && i == 0) {
        int2 ce = __ldg((const int2*)cand + (C - 1));
        float z = d_sc[ce.x].x + d_sc[ce.y].y + b;
        out[C - 1] = 1.f / (1.f + __expf(-z));
    }
}

extern "C" void kernel_launch(void* const* d_in, const int* in_sizes, int n_in,
                              void* d_out, int out_size) {
    const float* x    = (const float*)d_in[0];
    const int*   ei   = (const int*)d_in[1];
    const int*   cand = (const int*)d_in[2];
    const float* w1a = (const float*)d_in[3];
    const float* b1a = (const float*)d_in[4];
    const float* w2a = (const float*)d_in[5];
    const float* b2a = (const float*)d_in[6];
    const float* w1b = (const float*)d_in[7];
    const float* b1b = (const float*)d_in[8];
    const float* w2b = (const float*)d_in[9];
    const float* b2b = (const float*)d_in[10];
    const float* ws  = (const float*)d_in[11];
    const float* bs  = (const float*)d_in[12];

    int N = in_sizes[0] / 7;
    int E = in_sizes[1] / 2;
    int C = in_sizes[2] / 2;
    float* out = (float*)d_out;
    int NB = (N + SCAN_CHUNK - 1) / SCAN_CHUNK;
    int halfE = (E + 1) / 2;

    kH_hist <<<(halfE + 255) / 256, 256>>>(ei, x, E, N);
    kScan   <<<NB, 512>>>(N, NB);
    kP_place<<<(halfE + 255) / 256, 256>>>(ei, E, N);
    kE_agg1 <<<(N * 8 + 255) / 256, 256>>>(N);
    k2_mlpA <<<(N + 127) / 128, 128>>>(w1a, b1a, w2a, b2a, w1b, N);
    kF_agg2_mlpB<<<(N + 7) / 8, 256>>>(b1b, w2b, b2b, ws, N);
    k5_score<<<((C >> 1) + 255) / 256, 256>>>(cand, bs, out, C);
}